// round 13
// baseline (speedup 1.0000x reference)
#include <cuda_runtime.h>
#include <cstdint>
#include <cstddef>

#define RR 8
#define NN 300000
#define DD 128
#define AA 64
#define TILE_M 128
#define H_SLOT 4096            // words: 128 rows x 32 cols, XOR-swizzled
#define W_SLOT 2048            // words: 32 rows x 64 cols, XOR-swizzled
#define NCH 32                 // 8 relations x 4 k-chunks
#define LOG2E 1.4426950408889634f

__device__ __forceinline__ float fast_sigmoid(float x) {
    float t;
    asm("tanh.approx.f32 %0, %1;" : "=f"(t) : "f"(0.5f * x));
    return fmaf(t, 0.5f, 0.5f);
}
__device__ __forceinline__ float fast_exp(float x) {
    float e; asm("ex2.approx.f32 %0, %1;" : "=f"(e) : "f"(LOG2E * x));
    return e;
}

__device__ __forceinline__ void mma_tf32_16n8k8(float c[4],
                                                const unsigned a[4],
                                                unsigned b0, unsigned b1) {
    asm volatile(
        "mma.sync.aligned.m16n8k8.row.col.f32.tf32.tf32.f32 "
        "{%0,%1,%2,%3}, {%4,%5,%6,%7}, {%8,%9}, {%0,%1,%2,%3};"
        : "+f"(c[0]), "+f"(c[1]), "+f"(c[2]), "+f"(c[3])
        : "r"(a[0]), "r"(a[1]), "r"(a[2]), "r"(a[3]), "r"(b0), "r"(b1));
}

__device__ __forceinline__ void cp_async16_s(uint32_t dst, const float* src) {
    asm volatile("cp.async.cg.shared.global [%0], [%1], 16;"
                 :: "r"(dst), "l"(src));
}
#define CP_COMMIT() asm volatile("cp.async.commit_group;")
#define CP_WAIT(n)  asm volatile("cp.async.wait_group %0;" :: "n"(n))

__device__ __forceinline__ float4 ldcs4(const float4* p) {
    float4 v;
    asm volatile("ld.global.cs.v4.f32 {%0,%1,%2,%3}, [%4];"
                 : "=f"(v.x), "=f"(v.y), "=f"(v.z), "=f"(v.w) : "l"(p));
    return v;
}
__device__ __forceinline__ void stcs4(float4* p, float4 v) {
    asm volatile("st.global.cs.v4.f32 [%0], {%1,%2,%3,%4};"
                 :: "l"(p), "f"(v.x), "f"(v.y), "f"(v.z), "f"(v.w));
}

__device__ __forceinline__ uint32_t smem_u32(const void* p) {
    uint32_t a;
    asm("{ .reg .u64 t; cvta.to.shared.u64 t, %1; cvt.u32.u64 %0, t; }"
        : "=r"(a) : "l"(p));
    return a;
}

__global__ void __launch_bounds__(256, 3)
fused_kernel(const float* __restrict__ h,
             const float* __restrict__ w1,
             const float* __restrict__ w2,
             float* __restrict__ out) {
    extern __shared__ float smem[];
    float* sh_h   = smem;                       // 3 * H_SLOT
    float* sh_w   = sh_h + 3 * H_SLOT;          // 2 * W_SLOT
    float* sh_w2  = sh_w + 2 * W_SLOT;          // 512
    float* sh_sc  = sh_w2 + RR * AA;            // 8 * 128
    float* sh_prt = sh_sc + RR * TILE_M;        // 2 * 128

    const int tid = threadIdx.x;
    const long node0 = (long)blockIdx.x * TILE_M;
    const bool boundary = (node0 + TILE_M > NN);   // true for 1 block only

    sh_w2[tid] = w2[tid];
    sh_w2[tid + 256] = w2[tid + 256];

    // ---- per-thread staging constants (XOR-swizzled destinations) ----
    // h piece i: idx = tid + i*256, row = idx>>3 (32 rows/piece), c4 = idx&7
    const int hrow0 = tid >> 3, hc4 = tid & 7;
    const size_t hoff0 = (size_t)(node0 + hrow0) * DD + hc4 * 4;
    const uint32_t hB = smem_u32(sh_h);
    // swizzled word offset within slot for (hrow0 + i*32, hc4): row*32 + ((4*c4) ^ ((row&7)<<2))
    // (row&7) is invariant in i since rows step by 32
    const uint32_t hsw = (uint32_t)((hc4 * 4) ^ ((hrow0 & 7) << 2));
    const uint32_t hdst0 = hB + (uint32_t)(hrow0 * 32 + hsw) * 4;   // + i*(32*32*4) per piece
    // w piece i: idx = tid + i*256, row = idx>>4 (16 rows/piece), c4 = idx&15
    const int wrow0 = tid >> 4, wc4 = tid & 15;
    const size_t woff0 = (size_t)wrow0 * AA + wc4 * 4;
    const uint32_t wB = smem_u32(sh_w);
    const uint32_t wsw = (uint32_t)((wc4 * 4) ^ ((wrow0 & 3) << 3));
    const uint32_t wdst0 = wB + (uint32_t)(wrow0 * 64 + wsw) * 4;   // + i*(16*64*4) per piece

    const size_t NND = (size_t)NN * DD;

    // per-piece global h offset (clamped only in the boundary block)
    auto h_off = [&](int i) -> size_t {
        if (!boundary) return hoff0 + (size_t)i * (32 * DD);
        long node = node0 + hrow0 + i * 32;
        if (node >= NN) node = NN - 1;
        return (size_t)node * DD + hc4 * 4;
    };

    // stage all 4 h pieces of chunk c (used in prologue)
    auto stage_h_full = [&](int c) {
        const float* hs = h + (size_t)(c >> 2) * NND + (c & 3) * 32;
        uint32_t d = hdst0 + (uint32_t)((c % 3) * H_SLOT * 4);
        #pragma unroll
        for (int i = 0; i < 4; i++)
            cp_async16_s(d + i * (32 * 32 * 4), hs + h_off(i));
    };
    auto stage_w_full = [&](int c) {
        const float* ws = w1 + (size_t)(c >> 2) * (DD * AA) + (c & 3) * (32 * AA);
        uint32_t d = wdst0 + (uint32_t)((c & 1) * W_SLOT * 4);
        #pragma unroll
        for (int i = 0; i < 2; i++)
            cp_async16_s(d + i * (16 * 64 * 4), ws + woff0 + i * (16 * AA));
    };

    // prologue: groups [H0], [W0], [H1]  (order matters for wait_group math)
    stage_h_full(0); CP_COMMIT();
    stage_w_full(0); CP_COMMIT();
    stage_h_full(1); CP_COMMIT();

    const int w = tid >> 5, lane = tid & 31;
    const int g = lane >> 2, tg = lane & 3;
    const int m0 = (w & 3) * 32;   // 4-way m split
    const int nh = w >> 2;         // 2-way n split
    const int gx = g << 2;         // A-frag column swizzle (row&7 == g)
    // B-frag swizzled n-indices per nt (k&3 == tg for both b0 and b1 rows)
    int nsw[4];
    #pragma unroll
    for (int nt = 0; nt < 4; nt++)
        nsw[nt] = (nh * 32 + nt * 8 + g) ^ (tg << 3);

    float acc[2][4][4];

    for (int c = 0; c < NCH; c++) {
        const int kc = c & 3;

        // H(c) committed 2 iters ago, W(c) 1 iter ago; newest group = H(c+1) may stay
        if (c == NCH - 1) { CP_WAIT(0); } else { CP_WAIT(1); }
        __syncthreads();   // publish h slot c%3 + w slot c&1; order prior epoch

        // lag-1 score write: relation (c-1)/4 finished its epilogue in iter c-1
        if (c >= 1 && (c & 3) == 0 && tid < TILE_M)
            sh_sc[((c - 1) >> 2) * TILE_M + tid] = sh_prt[tid] + sh_prt[TILE_M + tid];

        if (kc == 0) {
            #pragma unroll
            for (int mt = 0; mt < 2; mt++)
                #pragma unroll
                for (int nt = 0; nt < 4; nt++)
                    #pragma unroll
                    for (int q = 0; q < 4; q++) acc[mt][nt][q] = 0.f;
        }

        const unsigned* hh = (const unsigned*)(sh_h + (c % 3) * H_SLOT);
        const unsigned* ww = (const unsigned*)(sh_w + (c & 1) * W_SLOT);

        // staging sources/dests for W(c+1) and H(c+2)
        const bool doW = (c + 1 < NCH), doH = (c + 2 < NCH);
        const float* wsn = nullptr; uint32_t wdn = 0;
        const float* hsn = nullptr; uint32_t hdn = 0;
        if (doW) {
            int cn = c + 1;
            wsn = w1 + (size_t)(cn >> 2) * (DD * AA) + (cn & 3) * (32 * AA);
            wdn = wdst0 + (uint32_t)((cn & 1) * W_SLOT * 4);
        }
        if (doH) {
            int cn = c + 2;
            hsn = h + (size_t)(cn >> 2) * NND + (cn & 3) * 32;
            hdn = hdst0 + (uint32_t)((cn % 3) * H_SLOT * 4);
        }

        #pragma unroll
        for (int kt = 0; kt < 4; kt++) {
            // de-burst staging: W(c+1) at kt=0 (commit), H(c+2) at kt=1,2 (commit at 2)
            if (kt == 0 && doW) {
                cp_async16_s(wdn, wsn + woff0);
                cp_async16_s(wdn + 16 * 64 * 4, wsn + woff0 + 16 * AA);
                CP_COMMIT();
            } else if (kt == 1 && doH) {
                cp_async16_s(hdn, hsn + h_off(0));
                cp_async16_s(hdn + 32 * 32 * 4, hsn + h_off(1));
            } else if (kt == 2 && doH) {
                cp_async16_s(hdn + 2 * 32 * 32 * 4, hsn + h_off(2));
                cp_async16_s(hdn + 3 * 32 * 32 * 4, hsn + h_off(3));
                CP_COMMIT();
            }
            unsigned a[2][4];
            #pragma unroll
            for (int mt = 0; mt < 2; mt++) {
                int row = m0 + mt * 16 + g;
                int col0 = (kt * 8 + tg) ^ gx;
                int col1 = (kt * 8 + tg + 4) ^ gx;
                a[mt][0] = hh[row * 32 + col0];
                a[mt][1] = hh[(row + 8) * 32 + col0];
                a[mt][2] = hh[row * 32 + col1];
                a[mt][3] = hh[(row + 8) * 32 + col1];
            }
            #pragma unroll
            for (int nt = 0; nt < 4; nt++) {
                unsigned b0 = ww[(kt * 8 + tg) * 64 + nsw[nt]];
                unsigned b1 = ww[(kt * 8 + tg + 4) * 64 + nsw[nt]];
                mma_tf32_16n8k8(acc[0][nt], a[0], b0, b1);
                mma_tf32_16n8k8(acc[1][nt], a[1], b0, b1);
            }
        }

        if (kc == 3) {
            const int r = c >> 2;
            float slo[2] = {0.f, 0.f}, shi[2] = {0.f, 0.f};
            #pragma unroll
            for (int mt = 0; mt < 2; mt++)
                #pragma unroll
                for (int nt = 0; nt < 4; nt++) {
                    int cb = nh * 32 + nt * 8 + 2 * tg;
                    float wa = sh_w2[r * AA + cb], wb2 = sh_w2[r * AA + cb + 1];
                    slo[mt] += fast_sigmoid(acc[mt][nt][0]) * wa + fast_sigmoid(acc[mt][nt][1]) * wb2;
                    shi[mt] += fast_sigmoid(acc[mt][nt][2]) * wa + fast_sigmoid(acc[mt][nt][3]) * wb2;
                }
            #pragma unroll
            for (int o = 1; o < 4; o <<= 1) {
                slo[0] += __shfl_xor_sync(0xffffffffu, slo[0], o);
                slo[1] += __shfl_xor_sync(0xffffffffu, slo[1], o);
                shi[0] += __shfl_xor_sync(0xffffffffu, shi[0], o);
                shi[1] += __shfl_xor_sync(0xffffffffu, shi[1], o);
            }
            if (tg == 0) {
                #pragma unroll
                for (int mt = 0; mt < 2; mt++) {
                    sh_prt[nh * TILE_M + m0 + mt * 16 + g]     = slo[mt];
                    sh_prt[nh * TILE_M + m0 + mt * 16 + g + 8] = shi[mt];
                }
            }
        }
    }
    __syncthreads();   // prt for r=7 complete; ring slots final

    // final score (r=7) + softmax over relations
    if (tid < TILE_M) {
        float sv[RR];
        sv[7] = sh_prt[tid] + sh_prt[TILE_M + tid];
        float m = sv[7];
        #pragma unroll
        for (int r = 0; r < 7; r++) { sv[r] = sh_sc[r * TILE_M + tid]; m = fmaxf(m, sv[r]); }
        float sum = 0.f;
        #pragma unroll
        for (int r = 0; r < RR; r++) { sv[r] = fast_exp(sv[r] - m); sum += sv[r]; }
        float inv = 1.f / sum;
        #pragma unroll
        for (int r = 0; r < RR; r++) sh_sc[r * TILE_M + tid] = sv[r] * inv;
    }
    __syncthreads();

    // phase 3: weighted sum. Ring holds r=7 chunks 29,30,31 in slots 2,0,1
    // (k[32:64), k[64:96), k[96:128)); k[0:32) + r=6..0 via .cs from L2/DRAM.
    const float4* hp = (const float4*)h;
    float4* op = (float4*)out;
    #pragma unroll 4
    for (int i = 0; i < 16; i++) {
        int idx = tid + i * 256;
        int nrow = idx >> 5, c4 = idx & 31;
        long node = node0 + nrow;
        if (node >= NN) continue;

        float a[RR];
        #pragma unroll
        for (int r = 0; r < RR; r++) a[r] = sh_sc[r * TILE_M + nrow];

        float4 acc4;
        {
            float4 v;
            if (c4 < 8) {
                v = ldcs4(&hp[((size_t)7 * NN + node) * 32 + c4]);
            } else {
                const int slot_of[4] = {0, 2, 0, 1};   // chunk group 1,2,3 -> slots 2,0,1
                int sw = (4 * (c4 & 7)) ^ ((nrow & 7) << 2);
                const float* sp = sh_h + slot_of[c4 >> 3] * H_SLOT + nrow * 32 + sw;
                v = *(const float4*)sp;
            }
            acc4.x = a[7] * v.x; acc4.y = a[7] * v.y;
            acc4.z = a[7] * v.z; acc4.w = a[7] * v.w;
        }
        #pragma unroll
        for (int r = 6; r >= 0; r--) {
            float4 v = ldcs4(&hp[((size_t)r * NN + node) * 32 + c4]);
            acc4.x += a[r] * v.x; acc4.y += a[r] * v.y;
            acc4.z += a[r] * v.z; acc4.w += a[r] * v.w;
        }
        stcs4(&op[(size_t)node * 32 + c4], acc4);
    }
}

extern "C" void kernel_launch(void* const* d_in, const int* in_sizes, int n_in,
                              void* d_out, int out_size) {
    const float* h  = (const float*)d_in[0];
    const float* w1 = (const float*)d_in[1];
    const float* w2 = (const float*)d_in[2];
    float* out = (float*)d_out;

    const int smem_bytes =
        (3 * H_SLOT + 2 * W_SLOT + RR * AA + RR * TILE_M + 2 * TILE_M) * 4;  // 72,704 B
    cudaFuncSetAttribute(fused_kernel,
                         cudaFuncAttributeMaxDynamicSharedMemorySize, smem_bytes);

    dim3 grid((NN + TILE_M - 1) / TILE_M);
    fused_kernel<<<grid, 256, smem_bytes>>>(h, w1, w2, out);
}